// round 10
// baseline (speedup 1.0000x reference)
#include <cuda_runtime.h>
#include <math.h>

#define K_DIM   76800           // 3*160*160
#define NGROUP  19200           // groups of 4 columns
#define NBATCH  1024
#define NOUT    8
#define THREADS 384             // 12 warps; 2 CTAs/SM -> 24 warps/SM
#define WARPS   12
#define NITER   (NGROUP / THREADS)   // 50 exact
#define EPS_F   1e-5f
#define MAGIC   12582912.0f     // 2^23 + 2^22

// ---------------- device scratch ----------------
#define MEAN_BLKS 512
__device__ float  g_mp[MEAN_BLKS];
__device__ float  g_wscale;               // fl(1/clip(mean|W|,eps))
__device__ float  g_c;                    // tf32(fl(1/g_wscale))
__device__ int    g_wpack[NGROUP * NOUT]; // packed ternary weights (s8 x4)

// ---------------- ptx helpers ----------------
__device__ __forceinline__ float tf32_rna(float x) {
    unsigned u;
    asm("cvt.rna.tf32.f32 %0, %1;" : "=r"(u) : "f"(x));
    return __uint_as_float(u);
}
__device__ __forceinline__ int dp4a_ss(unsigned a, int b, int c) {
    asm("dp4a.s32.s32 %0, %1, %2, %3;" : "=r"(c) : "r"(a), "r"(b), "r"(c));
    return c;
}
__device__ __forceinline__ int dp2a_lo_us(unsigned a, int b, int c) {
    asm("dp2a.lo.u32.s32 %0, %1, %2, %3;" : "=r"(c) : "r"(a), "r"(b), "r"(c));
    return c;
}
__device__ __forceinline__ int dp2a_hi_us(unsigned a, int b, int c) {
    asm("dp2a.hi.u32.s32 %0, %1, %2, %3;" : "=r"(c) : "r"(a), "r"(b), "r"(c));
    return c;
}
__device__ __forceinline__ unsigned prmt(unsigned a, unsigned b, unsigned s) {
    unsigned d;
    asm("prmt.b32 %0, %1, %2, %3;" : "=r"(d) : "r"(a), "r"(b), "r"(s));
    return d;
}

// ---------------- W pipeline (validated: ~5.5us + ~2.5us) ----------------
__global__ void wmean_kernel(const float* __restrict__ W) {
    const float4* W4 = (const float4*)W;
    const int n4 = NOUT * K_DIM / 4;   // 153600
    float s = 0.f;
    for (int i = blockIdx.x * blockDim.x + threadIdx.x; i < n4;
         i += gridDim.x * blockDim.x) {
        float4 v = W4[i];
        s += ((fabsf(v.x) + fabsf(v.y)) + (fabsf(v.z) + fabsf(v.w)));
    }
    __shared__ float sh[256];
    sh[threadIdx.x] = s;
    __syncthreads();
    for (int off = 128; off > 0; off >>= 1) {
        if (threadIdx.x < off) sh[threadIdx.x] += sh[threadIdx.x + off];
        __syncthreads();
    }
    if (threadIdx.x == 0) g_mp[blockIdx.x] = sh[0];
}

__global__ void wpack_kernel(const float* __restrict__ W) {
    __shared__ double sh[256];
    __shared__ float s_wsc;
    int t = threadIdx.x;
    sh[t] = (double)g_mp[t] + (double)g_mp[t + 256];
    __syncthreads();
    for (int off = 128; off > 0; off >>= 1) {
        if (t < off) sh[t] += sh[t + off];
        __syncthreads();
    }
    if (t == 0) {
        float sumf = (float)sh[0];
        float mean = __fdiv_rn(sumf, (float)(NOUT * K_DIM));
        float mcl  = fmaxf(mean, EPS_F);
        float wsc  = __fdiv_rn(1.0f, mcl);
        s_wsc = wsc;
        if (blockIdx.x == 0) {
            g_wscale = wsc;
            g_c = tf32_rna(__fdiv_rn(1.0f, wsc));
        }
    }
    __syncthreads();
    float wscale = s_wsc;

    int g = blockIdx.x * blockDim.x + t;
    if (g >= NGROUP) return;
    int col = g * 4;
    #pragma unroll
    for (int o = 0; o < NOUT; o++) {
        const float* wr = W + o * K_DIM + col;
        int p = 0;
        #pragma unroll
        for (int j = 0; j < 4; j++) {
            int tt = __float2int_rn(__fmul_rn(wr[j], wscale));
            tt = max(-1, min(1, tt));
            p |= (tt & 0xff) << (8 * j);
        }
        g_wpack[g * NOUT + o] = p;
    }
}

// ---------------- main fused kernel: ONE ROW per CTA, 2 CTAs/SM ------------
// dynamic smem: LUT int[256][32] = 32KB (+ pad to 100KB forcing 2 CTAs/SM)
extern __shared__ int s_lut[];

// exact reference rounding: q = rn_half_even(fl(x*s)); no FFMA contraction
#define QIDX(v, sv) \
    (__float_as_int(__fadd_rn(__fmul_rn((v), (sv)), MAGIC)) - 0x4B400000)

#define BODY(a, wA, wB, sv, lp, aL, aH)                                        \
    do {                                                                       \
        int q0 = QIDX((a).x, sv);                                              \
        int q1 = QIDX((a).y, sv);                                              \
        int q2 = QIDX((a).z, sv);                                              \
        int q3 = QIDX((a).w, sv);                                              \
        unsigned R0 = (unsigned)(lp)[q0 << 5];                                 \
        unsigned R1 = (unsigned)(lp)[q1 << 5];                                 \
        unsigned R2 = (unsigned)(lp)[q2 << 5];                                 \
        unsigned R3 = (unsigned)(lp)[q3 << 5];                                 \
        unsigned lo = prmt(R0, R1, 0x5410);                                    \
        unsigned hi = prmt(R2, R3, 0x5410);                                    \
        unsigned hp = prmt(prmt(R0, R1, 0x0062), prmt(R2, R3, 0x0062), 0x5410);\
        aL[0] = dp2a_lo_us(lo, (wA).x, aL[0]); aL[0] = dp2a_hi_us(hi, (wA).x, aL[0]); aH[0] = dp4a_ss(hp, (wA).x, aH[0]); \
        aL[1] = dp2a_lo_us(lo, (wA).y, aL[1]); aL[1] = dp2a_hi_us(hi, (wA).y, aL[1]); aH[1] = dp4a_ss(hp, (wA).y, aH[1]); \
        aL[2] = dp2a_lo_us(lo, (wA).z, aL[2]); aL[2] = dp2a_hi_us(hi, (wA).z, aL[2]); aH[2] = dp4a_ss(hp, (wA).z, aH[2]); \
        aL[3] = dp2a_lo_us(lo, (wA).w, aL[3]); aL[3] = dp2a_hi_us(hi, (wA).w, aL[3]); aH[3] = dp4a_ss(hp, (wA).w, aH[3]); \
        aL[4] = dp2a_lo_us(lo, (wB).x, aL[4]); aL[4] = dp2a_hi_us(hi, (wB).x, aL[4]); aH[4] = dp4a_ss(hp, (wB).x, aH[4]); \
        aL[5] = dp2a_lo_us(lo, (wB).y, aL[5]); aL[5] = dp2a_hi_us(hi, (wB).y, aL[5]); aH[5] = dp4a_ss(hp, (wB).y, aH[5]); \
        aL[6] = dp2a_lo_us(lo, (wB).z, aL[6]); aL[6] = dp2a_hi_us(hi, (wB).z, aL[6]); aH[6] = dp4a_ss(hp, (wB).z, aH[6]); \
        aL[7] = dp2a_lo_us(lo, (wB).w, aL[7]); aL[7] = dp2a_hi_us(hi, (wB).w, aL[7]); aH[7] = dp4a_ss(hp, (wB).w, aH[7]); \
    } while (0)

__global__ void __launch_bounds__(THREADS, 2)
main_kernel(const float* __restrict__ x, float* __restrict__ out) {
    __shared__ float s_wmax[WARPS];
    __shared__ float s_scale;
    __shared__ int   s_gexp;
    __shared__ unsigned long long s_acc[NOUT];

    const int tid = threadIdx.x;
    const int wid = tid >> 5, lid = tid & 31;
    const int row = blockIdx.x;

    const float4* __restrict__ xr = (const float4*)(x + (size_t)row * K_DIM);

    // ---- pass 1: max |x| over this row (DRAM stream -> lands in L2) ----
    float m = 0.f;
    #pragma unroll 5
    for (int g = tid; g < NGROUP; g += THREADS) {
        float4 a = xr[g];
        m = fmaxf(m, fmaxf(fmaxf(fabsf(a.x), fabsf(a.y)),
                           fmaxf(fabsf(a.z), fabsf(a.w))));
    }
    #pragma unroll
    for (int off = 16; off > 0; off >>= 1)
        m = fmaxf(m, __shfl_xor_sync(0xffffffffu, m, off));
    if (lid == 0) s_wmax[wid] = m;
    if (tid < NOUT) s_acc[tid] = 0ull;
    __syncthreads();
    if (tid == 0) {
        float mm = s_wmax[0];
        #pragma unroll
        for (int i = 1; i < WARPS; i++) mm = fmaxf(mm, s_wmax[i]);
        s_scale = __fdiv_rn(127.0f, fmaxf(mm, EPS_F));   // == reference
    }
    __syncthreads();
    const float sv = s_scale;

    // ---- build tf32 LUT: R[q] = tf32(fl(q/scale)) / 2^gexp (exact int) ----
    if (tid < 256) {
        int qb = tid;                 // q = qb - 128
        int q  = qb - 128;
        float t1 = tf32_rna(__fdiv_rn(1.0f, sv));
        int gexp = ilogbf(t1) - 10;
        int R = 0;
        if (q != -128) {
            float rr = __fdiv_rn((float)q, sv);
            float t  = tf32_rna(rr);
            R = __float2int_rn(ldexpf(t, -gexp));
        }
        if (qb == 129) s_gexp = gexp;
        int* dst = s_lut + qb * 32;
        #pragma unroll
        for (int l = 0; l < 32; l++) dst[l] = R;   // lane-replicated
    }
    __syncthreads();

    // ---- pass 2: plain R2-style loop (x from L2, W from L2) ----
    int aL[NOUT] = {0,0,0,0,0,0,0,0};
    int aH[NOUT] = {0,0,0,0,0,0,0,0};
    const int4* __restrict__ wp = (const int4*)g_wpack;
    const int* __restrict__ lp = s_lut + 4096 + lid;   // q=0 centered

    #pragma unroll 5
    for (int g = tid; g < NGROUP; g += THREADS) {
        float4 a = xr[g];
        int4 wA = wp[2 * g];
        int4 wB = wp[2 * g + 1];
        BODY(a, wA, wB, sv, lp, aL, aH);
    }

    // ---- exact integer reduction ----
    #pragma unroll
    for (int o = 0; o < NOUT; o++) {
        int L = __reduce_add_sync(0xffffffffu, aL[o]);
        int H = __reduce_add_sync(0xffffffffu, aH[o]);
        if (lid == 0) {
            long long v = (long long)H * 65536ll + (long long)L;
            atomicAdd(&s_acc[o], (unsigned long long)v);
        }
    }
    __syncthreads();

    // ---- softmax (exact tf32-emulated logits) ----
    if (tid == 0) {
        float fs = ldexpf(1.0f, s_gexp);
        float c  = g_c;
        float y[NOUT];
        float mx = -3.0e38f;
        #pragma unroll
        for (int o = 0; o < NOUT; o++) {
            long long S = (long long)s_acc[o];
            y[o] = ((float)S * fs) * c;
            mx = fmaxf(mx, y[o]);
        }
        float se = 0.f;
        #pragma unroll
        for (int o = 0; o < NOUT; o++) {
            y[o] = expf(y[o] - mx);
            se += y[o];
        }
        float inv = 1.0f / se;
        #pragma unroll
        for (int o = 0; o < NOUT; o++)
            out[(size_t)row * NOUT + o] = y[o] * inv;
    }
}

// ---------------- launch ----------------
extern "C" void kernel_launch(void* const* d_in, const int* in_sizes, int n_in,
                              void* d_out, int out_size) {
    const float* x = (const float*)d_in[0];
    const float* W = (const float*)d_in[1];
    if (n_in >= 2 && in_sizes[0] == NOUT * K_DIM && in_sizes[1] == NBATCH * K_DIM) {
        x = (const float*)d_in[1];
        W = (const float*)d_in[0];
    }
    float* out = (float*)d_out;

    // 100KB dyn smem (32KB LUT + pad): exactly 2 CTAs/SM (228KB cap).
    // Co-resident CTAs at different phases overlap DRAM (pass1) with issue (pass2).
    const int dyn = 100 * 1024;
    cudaFuncSetAttribute(main_kernel,
                         cudaFuncAttributeMaxDynamicSharedMemorySize, dyn);

    wmean_kernel<<<MEAN_BLKS, 256>>>(W);
    wpack_kernel<<<NGROUP / 256, 256>>>(W);
    main_kernel<<<NBATCH, THREADS, dyn>>>(x, out);
}

// round 11
// speedup vs baseline: 1.1688x; 1.1688x over previous
#include <cuda_runtime.h>
#include <math.h>

#define K_DIM   76800           // 3*160*160
#define NGROUP  (K_DIM / 4)     // 19200 groups of 4 columns
#define NBATCH  1024
#define NOUT    8
#define THREADS 768
#define ROWS    2
#define EPS_F   1e-5f

// ---------------- device scratch ----------------
#define MEAN_BLKS 512
__device__ float  g_mp[MEAN_BLKS];
__device__ float  g_wscale;               // fl(1/clip(mean|W|,eps))  (matches ref)
__device__ float  g_c;                    // tf32(fl(1/g_wscale)) = tf32 of |wq|
__device__ int    g_wpack[NGROUP * NOUT]; // packed ternary weights (s8 x4)

// ---------------- ptx helpers ----------------
__device__ __forceinline__ float tf32_rna(float x) {
    unsigned u;
    asm("cvt.rna.tf32.f32 %0, %1;" : "=r"(u) : "f"(x));
    return __uint_as_float(u);
}
__device__ __forceinline__ int dp4a_ss(unsigned a, int b, int c) {
    asm("dp4a.s32.s32 %0, %1, %2, %3;" : "=r"(c) : "r"(a), "r"(b), "r"(c));
    return c;
}
__device__ __forceinline__ int dp2a_lo_us(unsigned a, int b, int c) {
    asm("dp2a.lo.u32.s32 %0, %1, %2, %3;" : "=r"(c) : "r"(a), "r"(b), "r"(c));
    return c;
}
__device__ __forceinline__ int dp2a_hi_us(unsigned a, int b, int c) {
    asm("dp2a.hi.u32.s32 %0, %1, %2, %3;" : "=r"(c) : "r"(a), "r"(b), "r"(c));
    return c;
}
__device__ __forceinline__ unsigned prmt(unsigned a, unsigned b, unsigned s) {
    unsigned d;
    asm("prmt.b32 %0, %1, %2, %3;" : "=r"(d) : "r"(a), "r"(b), "r"(s));
    return d;
}

// ---------------- W pipeline (validated fast prep: ~5.3us + ~2.5us) --------
__global__ void wmean_kernel(const float* __restrict__ W) {
    const float4* W4 = (const float4*)W;
    const int n4 = NOUT * K_DIM / 4;   // 153600
    float s = 0.f;
    for (int i = blockIdx.x * blockDim.x + threadIdx.x; i < n4;
         i += gridDim.x * blockDim.x) {
        float4 v = W4[i];
        s += ((fabsf(v.x) + fabsf(v.y)) + (fabsf(v.z) + fabsf(v.w)));
    }
    __shared__ float sh[256];
    sh[threadIdx.x] = s;
    __syncthreads();
    for (int off = 128; off > 0; off >>= 1) {
        if (threadIdx.x < off) sh[threadIdx.x] += sh[threadIdx.x + off];
        __syncthreads();
    }
    if (threadIdx.x == 0) g_mp[blockIdx.x] = sh[0];
}

// final mean-reduction folded in (every block redundantly reduces g_mp)
__global__ void wpack_kernel(const float* __restrict__ W) {
    __shared__ double sh[256];
    __shared__ float s_wsc;
    int t = threadIdx.x;
    sh[t] = (double)g_mp[t] + (double)g_mp[t + 256];
    __syncthreads();
    for (int off = 128; off > 0; off >>= 1) {
        if (t < off) sh[t] += sh[t + off];
        __syncthreads();
    }
    if (t == 0) {
        float sumf = (float)sh[0];
        float mean = __fdiv_rn(sumf, (float)(NOUT * K_DIM));
        float mcl  = fmaxf(mean, EPS_F);                  // jnp.clip(mean, EPS)
        float wsc  = __fdiv_rn(1.0f, mcl);                // scale = 1/clip(mean)
        s_wsc = wsc;
        if (blockIdx.x == 0) {
            g_wscale = wsc;
            g_c = tf32_rna(__fdiv_rn(1.0f, wsc));         // tf32 of wq magnitude
        }
    }
    __syncthreads();
    float wscale = s_wsc;

    int g = blockIdx.x * blockDim.x + t;
    if (g >= NGROUP) return;
    int col = g * 4;
    #pragma unroll
    for (int o = 0; o < NOUT; o++) {
        const float* wr = W + o * K_DIM + col;
        int p = 0;
        #pragma unroll
        for (int j = 0; j < 4; j++) {
            int tt = __float2int_rn(__fmul_rn(wr[j], wscale)); // round half-even
            tt = max(-1, min(1, tt));
            p |= (tt & 0xff) << (8 * j);
        }
        g_wpack[g * NOUT + o] = p;
    }
}

// ---------------- main fused kernel (R2 verbatim: measured 115.5us) --------
// dynamic smem: lane-replicated LUT  int lut[2][256][32]  (64KB) + pad
extern __shared__ int s_lut[];

__global__ void __launch_bounds__(THREADS, 1)
main_kernel(const float* __restrict__ x, float* __restrict__ out) {
    __shared__ float s_wmax[ROWS][THREADS / 32];
    __shared__ float s_scale[ROWS];
    __shared__ int   s_gexp[ROWS];
    __shared__ unsigned long long s_acc[ROWS * NOUT];

    const int tid = threadIdx.x;
    const int wid = tid >> 5, lid = tid & 31;
    const int row0 = blockIdx.x * ROWS;

    const float4* __restrict__ xr0 = (const float4*)(x + (size_t)row0 * K_DIM);
    const float4* __restrict__ xr1 = (const float4*)(x + (size_t)(row0 + 1) * K_DIM);

    // ---- pass 1: per-row max |x| ----
    float m0 = 0.f, m1 = 0.f;
    #pragma unroll 5
    for (int g = tid; g < NGROUP; g += THREADS) {
        float4 a = xr0[g];
        float4 b = xr1[g];
        m0 = fmaxf(m0, fmaxf(fmaxf(fabsf(a.x), fabsf(a.y)),
                             fmaxf(fabsf(a.z), fabsf(a.w))));
        m1 = fmaxf(m1, fmaxf(fmaxf(fabsf(b.x), fabsf(b.y)),
                             fmaxf(fabsf(b.z), fabsf(b.w))));
    }
    #pragma unroll
    for (int off = 16; off > 0; off >>= 1) {
        m0 = fmaxf(m0, __shfl_xor_sync(0xffffffffu, m0, off));
        m1 = fmaxf(m1, __shfl_xor_sync(0xffffffffu, m1, off));
    }
    if (lid == 0) { s_wmax[0][wid] = m0; s_wmax[1][wid] = m1; }
    if (tid < ROWS * NOUT) s_acc[tid] = 0ull;
    __syncthreads();
    if (tid < ROWS) {
        float m = s_wmax[tid][0];
        #pragma unroll
        for (int i = 1; i < THREADS / 32; i++) m = fmaxf(m, s_wmax[tid][i]);
        s_scale[tid] = __fdiv_rn(127.0f, fmaxf(m, EPS_F));  // == reference scale
    }
    __syncthreads();
    const float s0 = s_scale[0];
    const float s1 = s_scale[1];

    // ---- build per-row tf32 LUT: R[q] = tf32(fl(q/scale)) / 2^gexp  (exact int) ----
    for (int e = tid; e < 2 * 256; e += THREADS) {
        int row = e >> 8;
        int qb  = e & 255;            // biased index, q = qb - 128
        int q   = qb - 128;
        float s = s_scale[row];
        float t1 = tf32_rna(__fdiv_rn(1.0f, s));   // smallest-magnitude tf32 value
        int gexp = ilogbf(t1) - 10;                // tf32 ulp exponent of t1
        int R = 0;
        if (q != -128) {
            float r = __fdiv_rn((float)q, s);      // exact match of xq = q/scale
            float t = tf32_rna(r);                 // exact match of GEMM tf32 round
            R = __float2int_rn(ldexpf(t, -gexp));  // exact integer representation
        }
        if (qb == 129) s_gexp[row] = gexp;         // thread owning q=1 records gexp
        int* dst = s_lut + row * 8192 + qb * 32;
        #pragma unroll
        for (int l = 0; l < 32; l++) dst[l] = R;   // lane-replicate: conflict-free LDS
    }
    __syncthreads();

    // ---- pass 2: quantize + LUT + integer (dp2a/dp4a) dot with ternary W ----
    int aL0[NOUT] = {0,0,0,0,0,0,0,0}, aH0[NOUT] = {0,0,0,0,0,0,0,0};
    int aL1[NOUT] = {0,0,0,0,0,0,0,0}, aH1[NOUT] = {0,0,0,0,0,0,0,0};
    const int4* __restrict__ wp = (const int4*)g_wpack;
    const int* __restrict__ l0 = s_lut + lid;
    const int* __restrict__ l1 = s_lut + 8192 + lid;

    for (int g = tid; g < NGROUP; g += THREADS) {
        float4 a = xr0[g];
        float4 b = xr1[g];
        int4 wA = wp[g * 2];
        int4 wB = wp[g * 2 + 1];

        // row 0
        {
            int q0 = __float2int_rn(a.x * s0) + 128;
            int q1 = __float2int_rn(a.y * s0) + 128;
            int q2 = __float2int_rn(a.z * s0) + 128;
            int q3 = __float2int_rn(a.w * s0) + 128;
            unsigned R0 = (unsigned)l0[q0 << 5];
            unsigned R1 = (unsigned)l0[q1 << 5];
            unsigned R2 = (unsigned)l0[q2 << 5];
            unsigned R3 = (unsigned)l0[q3 << 5];
            unsigned lo = prmt(R0, R1, 0x5410);                      // [L0,L1] u16x2
            unsigned hi = prmt(R2, R3, 0x5410);                      // [L2,L3] u16x2
            unsigned hp = prmt(prmt(R0, R1, 0x0062),
                               prmt(R2, R3, 0x0062), 0x5410);        // [H0..H3] s8x4
            aL0[0] = dp2a_lo_us(lo, wA.x, aL0[0]); aL0[0] = dp2a_hi_us(hi, wA.x, aL0[0]); aH0[0] = dp4a_ss(hp, wA.x, aH0[0]);
            aL0[1] = dp2a_lo_us(lo, wA.y, aL0[1]); aL0[1] = dp2a_hi_us(hi, wA.y, aL0[1]); aH0[1] = dp4a_ss(hp, wA.y, aH0[1]);
            aL0[2] = dp2a_lo_us(lo, wA.z, aL0[2]); aL0[2] = dp2a_hi_us(hi, wA.z, aL0[2]); aH0[2] = dp4a_ss(hp, wA.z, aH0[2]);
            aL0[3] = dp2a_lo_us(lo, wA.w, aL0[3]); aL0[3] = dp2a_hi_us(hi, wA.w, aL0[3]); aH0[3] = dp4a_ss(hp, wA.w, aH0[3]);
            aL0[4] = dp2a_lo_us(lo, wB.x, aL0[4]); aL0[4] = dp2a_hi_us(hi, wB.x, aL0[4]); aH0[4] = dp4a_ss(hp, wB.x, aH0[4]);
            aL0[5] = dp2a_lo_us(lo, wB.y, aL0[5]); aL0[5] = dp2a_hi_us(hi, wB.y, aL0[5]); aH0[5] = dp4a_ss(hp, wB.y, aH0[5]);
            aL0[6] = dp2a_lo_us(lo, wB.z, aL0[6]); aL0[6] = dp2a_hi_us(hi, wB.z, aL0[6]); aH0[6] = dp4a_ss(hp, wB.z, aH0[6]);
            aL0[7] = dp2a_lo_us(lo, wB.w, aL0[7]); aL0[7] = dp2a_hi_us(hi, wB.w, aL0[7]); aH0[7] = dp4a_ss(hp, wB.w, aH0[7]);
        }
        // row 1
        {
            int q0 = __float2int_rn(b.x * s1) + 128;
            int q1 = __float2int_rn(b.y * s1) + 128;
            int q2 = __float2int_rn(b.z * s1) + 128;
            int q3 = __float2int_rn(b.w * s1) + 128;
            unsigned R0 = (unsigned)l1[q0 << 5];
            unsigned R1 = (unsigned)l1[q1 << 5];
            unsigned R2 = (unsigned)l1[q2 << 5];
            unsigned R3 = (unsigned)l1[q3 << 5];
            unsigned lo = prmt(R0, R1, 0x5410);
            unsigned hi = prmt(R2, R3, 0x5410);
            unsigned hp = prmt(prmt(R0, R1, 0x0062),
                               prmt(R2, R3, 0x0062), 0x5410);
            aL1[0] = dp2a_lo_us(lo, wA.x, aL1[0]); aL1[0] = dp2a_hi_us(hi, wA.x, aL1[0]); aH1[0] = dp4a_ss(hp, wA.x, aH1[0]);
            aL1[1] = dp2a_lo_us(lo, wA.y, aL1[1]); aL1[1] = dp2a_hi_us(hi, wA.y, aL1[1]); aH1[1] = dp4a_ss(hp, wA.y, aH1[1]);
            aL1[2] = dp2a_lo_us(lo, wA.z, aL1[2]); aL1[2] = dp2a_hi_us(hi, wA.z, aL1[2]); aH1[2] = dp4a_ss(hp, wA.z, aH1[2]);
            aL1[3] = dp2a_lo_us(lo, wA.w, aL1[3]); aL1[3] = dp2a_hi_us(hi, wA.w, aL1[3]); aH1[3] = dp4a_ss(hp, wA.w, aH1[3]);
            aL1[4] = dp2a_lo_us(lo, wB.x, aL1[4]); aL1[4] = dp2a_hi_us(hi, wB.x, aL1[4]); aH1[4] = dp4a_ss(hp, wB.x, aH1[4]);
            aL1[5] = dp2a_lo_us(lo, wB.y, aL1[5]); aL1[5] = dp2a_hi_us(hi, wB.y, aL1[5]); aH1[5] = dp4a_ss(hp, wB.y, aH1[5]);
            aL1[6] = dp2a_lo_us(lo, wB.z, aL1[6]); aL1[6] = dp2a_hi_us(hi, wB.z, aL1[6]); aH1[6] = dp4a_ss(hp, wB.z, aH1[6]);
            aL1[7] = dp2a_lo_us(lo, wB.w, aL1[7]); aL1[7] = dp2a_hi_us(hi, wB.w, aL1[7]); aH1[7] = dp4a_ss(hp, wB.w, aH1[7]);
        }
    }

    // ---- exact integer reduction ----
    #pragma unroll
    for (int o = 0; o < NOUT; o++) {
        int L0 = __reduce_add_sync(0xffffffffu, aL0[o]);
        int H0 = __reduce_add_sync(0xffffffffu, aH0[o]);
        int L1 = __reduce_add_sync(0xffffffffu, aL1[o]);
        int H1 = __reduce_add_sync(0xffffffffu, aH1[o]);
        if (lid == 0) {
            long long v0 = (long long)H0 * 65536ll + (long long)L0;
            long long v1 = (long long)H1 * 65536ll + (long long)L1;
            atomicAdd(&s_acc[o],        (unsigned long long)v0);
            atomicAdd(&s_acc[NOUT + o], (unsigned long long)v1);
        }
    }
    __syncthreads();

    // ---- softmax (exact tf32-emulated logits) ----
    if (tid < ROWS) {
        float fs = ldexpf(1.0f, s_gexp[tid]);
        float c  = g_c;
        float y[NOUT];
        float mx = -3.0e38f;
        #pragma unroll
        for (int o = 0; o < NOUT; o++) {
            long long S = (long long)s_acc[tid * NOUT + o];
            y[o] = ((float)S * fs) * c;
            mx = fmaxf(mx, y[o]);
        }
        float se = 0.f;
        #pragma unroll
        for (int o = 0; o < NOUT; o++) {
            y[o] = expf(y[o] - mx);
            se += y[o];
        }
        float inv = 1.0f / se;
        #pragma unroll
        for (int o = 0; o < NOUT; o++)
            out[(size_t)(row0 + tid) * NOUT + o] = y[o] * inv;
    }
}

// ---------------- launch ----------------
extern "C" void kernel_launch(void* const* d_in, const int* in_sizes, int n_in,
                              void* d_out, int out_size) {
    const float* x = (const float*)d_in[0];
    const float* W = (const float*)d_in[1];
    if (n_in >= 2 && in_sizes[0] == NOUT * K_DIM && in_sizes[1] == NBATCH * K_DIM) {
        x = (const float*)d_in[1];
        W = (const float*)d_in[0];
    }
    float* out = (float*)d_out;

    // 120KB dynamic smem: 64KB LUT + pad forcing 1 CTA/SM (L2 residency of x)
    cudaFuncSetAttribute(main_kernel,
                         cudaFuncAttributeMaxDynamicSharedMemorySize, 120 * 1024);

    wmean_kernel<<<MEAN_BLKS, 256>>>(W);
    wpack_kernel<<<NGROUP / 256, 256>>>(W);
    main_kernel<<<NBATCH / ROWS, THREADS, 120 * 1024>>>(x, out);
}